// round 15
// baseline (speedup 1.0000x reference)
#include <cuda_runtime.h>
#include <cuda_fp16.h>
#include <cstdint>

#define D_MODEL 512
#define JOINT   640
#define VOCAB   1024
#define BB      4
#define TT      256
#define UU      64
#define M_TOTAL (BB*TT*UU)   // 65536

#define BK 32
#define NK (JOINT/BK)        // 20

// ---------------- scratch (no allocations allowed) ----------------
__device__ float  g_E[BB*TT*JOINT];       // permuted fp32 E projection
__device__ float  g_P[BB*UU*JOINT];       // permuted fp32 P projection
// Wt: fp16 out_w, m16n8k16 paired-B fragment order:
//   uint4 slot ((nblk*NK+kt)*1024 + nbp*64 + ks*32 + lane)
__device__ __half g_Wt[VOCAB*JOINT];
// Zf: fp16 tanh(E+P), A-fragment order:
//   uint4 slot ((bt*NK+kt)*256 + (rb*2+ks)*32 + lane)
__device__ __half g_Zf[(size_t)M_TOTAL*JOINT];

// ---------------- helpers ----------------
__device__ __forceinline__ float tanh_fast(float x) {
    float y;
    asm("tanh.approx.f32 %0, %1;" : "=f"(y) : "f"(x));
    return y;
}
__device__ __forceinline__ uint32_t smem_u32(const void* p) {
    return (uint32_t)__cvta_generic_to_shared(p);
}
__device__ __forceinline__ void cp_async16_cg(void* smem_dst, const void* gmem_src) {
    asm volatile("cp.async.cg.shared.global [%0], [%1], 16;\n"
                 :: "r"(smem_u32(smem_dst)), "l"(gmem_src));
}
__device__ __forceinline__ void cp_async16_ca(void* smem_dst, const void* gmem_src) {
    asm volatile("cp.async.ca.shared.global [%0], [%1], 16;\n"
                 :: "r"(smem_u32(smem_dst)), "l"(gmem_src));
}
#define CP_COMMIT() asm volatile("cp.async.commit_group;\n" ::: "memory")
#define CP_WAIT0()  asm volatile("cp.async.wait_group 0;\n" ::: "memory")
#define CP_WAIT1()  asm volatile("cp.async.wait_group 1;\n" ::: "memory")

// ---------------- projection tile into smem: sT[m][j] = X[m]·W[j] + b[j] ----
__device__ void proj_tile_smem(const float* __restrict__ X, const float* __restrict__ W,
                               const float* __restrict__ bias,
                               float (*sT)[68], int m0, int j0) {
    __shared__ float sX[16][68];   // [k][m]
    __shared__ float sW[16][68];   // [k][j]
    const int tid = threadIdx.x;
    const int tx = tid & 15, ty = tid >> 4;
    const int lrow = tid >> 2, lseg = tid & 3;

    float acc[4][4] = {};
    for (int k0 = 0; k0 < D_MODEL; k0 += 16) {
        float4 xv = *(const float4*)(X + (size_t)(m0 + lrow) * D_MODEL + k0 + lseg * 4);
        float4 wv = *(const float4*)(W + (size_t)(j0 + lrow) * D_MODEL + k0 + lseg * 4);
        sX[lseg * 4 + 0][lrow] = xv.x; sX[lseg * 4 + 1][lrow] = xv.y;
        sX[lseg * 4 + 2][lrow] = xv.z; sX[lseg * 4 + 3][lrow] = xv.w;
        sW[lseg * 4 + 0][lrow] = wv.x; sW[lseg * 4 + 1][lrow] = wv.y;
        sW[lseg * 4 + 2][lrow] = wv.z; sW[lseg * 4 + 3][lrow] = wv.w;
        __syncthreads();
#pragma unroll
        for (int k = 0; k < 16; k++) {
            float4 a = *(const float4*)(&sX[k][ty * 4]);
            float4 b = *(const float4*)(&sW[k][tx * 4]);
            float av[4] = { a.x, a.y, a.z, a.w };
            float bv[4] = { b.x, b.y, b.z, b.w };
#pragma unroll
            for (int i = 0; i < 4; i++)
#pragma unroll
                for (int j = 0; j < 4; j++) acc[i][j] += av[i] * bv[j];
        }
        __syncthreads();
    }
    float4 bv = *(const float4*)(bias + j0 + tx * 4);
    float bb[4] = { bv.x, bv.y, bv.z, bv.w };
#pragma unroll
    for (int i = 0; i < 4; i++)
#pragma unroll
        for (int j = 0; j < 4; j++)
            sT[ty * 4 + i][tx * 4 + j] = acc[i][j] + bb[j];
    __syncthreads();
}

// ---------------- kernel 1: projections only (E + P), permuted outputs -------
// bid [0,160): E proj tiles  [160,200): P proj tiles
__global__ void __launch_bounds__(256) prep_kernel(
    const float* __restrict__ enc,    const float* __restrict__ pred,
    const float* __restrict__ enc_w,  const float* __restrict__ enc_b,
    const float* __restrict__ pred_w, const float* __restrict__ pred_b,
    float* __restrict__ E, float* __restrict__ Pq) {
    const int bid = blockIdx.x;
    const int tid = threadIdx.x;
    __shared__ float sT[64][68];

    if (bid < 160) {
        int m0 = (bid / 10) * 64, j0 = (bid % 10) * 64;
        proj_tile_smem(enc, enc_w, enc_b, sT, m0, j0);
#pragma unroll
        for (int i = 0; i < 4; i++) {
            int sid = tid + 256 * i;
            int row = sid >> 4;
            int sl  = sid & 15;
            int kt_l = sl >> 3, ks = (sl >> 2) & 1, tg = sl & 3;
            int col = kt_l * 32 + ks * 16 + 2 * tg;
            float4 v;
            v.x = sT[row][col];     v.y = sT[row][col + 1];
            v.z = sT[row][col + 8]; v.w = sT[row][col + 9];
            *(float4*)(E + (size_t)(m0 + row) * JOINT + j0 + kt_l * 32
                         + (ks * 4 + tg) * 4) = v;
        }
    } else {
        int idx = bid - 160;                      // 40 tiles: 4 b x 10 j
        int b  = idx / 10;
        int j0 = (idx % 10) * 64;
        proj_tile_smem(pred, pred_w, pred_b, sT, b * 64, j0);
#pragma unroll
        for (int i = 0; i < 4; i++) {
            int sid = tid + 256 * i;
            int kt_l = sid >> 9;
            int pidx = sid & 511;
            int part = pidx >> 8;
            int ptid = pidx & 255;
            int blk = ptid >> 5;
            int rb = blk >> 1, ks = blk & 1;
            int g = (ptid >> 2) & 7, tg = ptid & 3;
            int u = rb * 16 + g + part * 8;
            int col = kt_l * 32 + ks * 16 + 2 * tg;
            float4 v;
            v.x = sT[u][col];     v.y = sT[u][col + 1];
            v.z = sT[u][col + 8]; v.w = sT[u][col + 9];
            *(float4*)(Pq + ((size_t)(b * NK + (j0 >> 5) + kt_l) * 512 + pidx) * 4) = v;
        }
    }
}

// ---------------- kernel 2: zgen (blocks 0..1023) + wprep (1024..1343) -------
__global__ void __launch_bounds__(256) zgen_kernel(
    const float* __restrict__ E, const float* __restrict__ P,
    const float* __restrict__ out_w,
    __half* __restrict__ Zf, __half* __restrict__ Wt) {
    const int tid = threadIdx.x;
    const int bid = blockIdx.x;

    if (bid >= 1024) {
        // ---- wprep: fp16-convert + paired-B fragment permute of out_w ----
        int s = (bid - 1024) * 256 + tid;         // 16B-slot index, 81920 total
        int lane = s & 31;
        int t1 = s >> 5;
        int ks  = t1 & 1;  t1 >>= 1;
        int nbp = t1 & 15; t1 >>= 4;
        int kt  = t1 % NK;
        int nblk = t1 / NK;
        int g = lane >> 2, tg = lane & 3;
        int v = nblk * 256 + nbp * 16 + g;
        int k = kt * 32 + ks * 16 + 2 * tg;
        const float* w0 = out_w + (size_t)v * JOINT;
        const float* w1 = w0 + (size_t)8 * JOINT;
        float2 aa = *(const float2*)(w0 + k);
        float2 ab = *(const float2*)(w0 + k + 8);
        float2 ba = *(const float2*)(w1 + k);
        float2 bb = *(const float2*)(w1 + k + 8);
        __half2 h0 = __floats2half2_rn(aa.x, aa.y);
        __half2 h1 = __floats2half2_rn(ab.x, ab.y);
        __half2 h2 = __floats2half2_rn(ba.x, ba.y);
        __half2 h3 = __floats2half2_rn(bb.x, bb.y);
        uint4 o;
        o.x = *(const uint32_t*)&h0; o.y = *(const uint32_t*)&h1;
        o.z = *(const uint32_t*)&h2; o.w = *(const uint32_t*)&h3;
        *(uint4*)(Wt + (size_t)s * 8) = o;
        return;
    }

    // ---- zgen: Zf = fp16(tanh(E+P)) in A-fragment order ----
    const int bt  = bid;
    const int b_  = bt >> 8;
    const int ks_p = (tid >> 5) & 1;
    const int tg_p = tid & 3;
    const float* gEp  = E + (size_t)bt * JOINT + (ks_p * 4 + tg_p) * 4;
    const float* gP0p = P + ((size_t)(b_ * NK) * 512 + tid) * 4;
    uint4* dst = (uint4*)Zf + (size_t)bt * NK * 256 + tid;

#pragma unroll 4
    for (int kt = 0; kt < NK; kt++) {
        float4 eV  = *(const float4*)(gEp  + (size_t)kt * 32);
        float4 p0V = *(const float4*)(gP0p + (size_t)kt * 2048);
        float4 p1V = *(const float4*)(gP0p + (size_t)kt * 2048 + 1024);
        __half2 a0 = __floats2half2_rn(tanh_fast(eV.x + p0V.x), tanh_fast(eV.y + p0V.y));
        __half2 a1 = __floats2half2_rn(tanh_fast(eV.x + p1V.x), tanh_fast(eV.y + p1V.y));
        __half2 a2 = __floats2half2_rn(tanh_fast(eV.z + p0V.z), tanh_fast(eV.w + p0V.w));
        __half2 a3 = __floats2half2_rn(tanh_fast(eV.z + p1V.z), tanh_fast(eV.w + p1V.w));
        uint4 st;
        st.x = *(const uint32_t*)&a0; st.y = *(const uint32_t*)&a1;
        st.z = *(const uint32_t*)&a2; st.w = *(const uint32_t*)&a3;
        dst[kt * 256] = st;
    }
}

// ---------------- kernel 3: 128x128 barrier-free GEMM, per-warp depth-2 ------
// 8 warps: wm = warp>>1 (0..3, 32-row slab), wn = warp&1 (0..1, 64-col slab).
// Per warp per chunk: 12 slots (4 A: mt*2+ks ; 8 B: 4+np*2+ks), 32 MMAs.
// smem: [warp][stage 0..1][slot 0..11][lane] uint4; 96KB -> 2 CTAs/SM.
// A via cp.async.cg (streamed); B via cp.async.ca (L1-resident, 160KB/nblk).
#define DSTAGE 2
#define SLOTS  12
#define GEMM_SMEM_BYTES (8 * DSTAGE * SLOTS * 32 * 16)   // 98304

__global__ void __launch_bounds__(256, 2) gemm_kernel(
    const __half* __restrict__ Zf, const __half* __restrict__ Wt,
    const float* __restrict__ out_b, float* __restrict__ out) {

    extern __shared__ uint4 smq[];

    const int tid  = threadIdx.x;
    const int warp = tid >> 5;
    const int lane = tid & 31;
    const int wm = warp >> 1;       // 0..3 : 32-row slab
    const int wn = warp & 1;        // 0..1 : 64-col slab

    // A: rows blockIdx.y*128 + wm*32 => bt = 2*blockIdx.y + (wm>>1), rb base (wm&1)*2
    const uint4* Ab = (const uint4*)Zf
        + ((size_t)(2 * blockIdx.y + (wm >> 1)) * NK) * 256
        + ((wm & 1) * 2) * 64 + lane;
    // B: cols blockIdx.x*128 + wn*64 => nblk = bx>>1, nbp base (bx&1)*8 + wn*4
    const uint4* Bb = (const uint4*)Wt
        + ((size_t)(blockIdx.x >> 1) * NK) * 1024
        + ((size_t)((blockIdx.x & 1) * 8 + wn * 4)) * 64 + lane;

    uint4* const ws = smq + (size_t)warp * (DSTAGE * SLOTS * 32) + lane;

    auto issue = [&](int kt, int stage) {
        uint4* dst = ws + stage * (SLOTS * 32);
        const uint4* a = Ab + (size_t)kt * 256;
        const uint4* b = Bb + (size_t)kt * 1024;
#pragma unroll
        for (int mt = 0; mt < 2; mt++)
#pragma unroll
            for (int ks = 0; ks < 2; ks++)
                cp_async16_cg(dst + (mt * 2 + ks) * 32, a + mt * 64 + ks * 32);
#pragma unroll
        for (int np = 0; np < 4; np++)
#pragma unroll
            for (int ks = 0; ks < 2; ks++)
                cp_async16_ca(dst + (4 + np * 2 + ks) * 32, b + np * 64 + ks * 32);
        CP_COMMIT();
    };

    float c[2][8][4];
#pragma unroll
    for (int mt = 0; mt < 2; mt++)
#pragma unroll
        for (int nt = 0; nt < 8; nt++)
#pragma unroll
            for (int qq = 0; qq < 4; qq++) c[mt][nt][qq] = 0.0f;

    auto consume = [&](int stage) {
        const uint4* s = ws + stage * (SLOTS * 32);
#pragma unroll
        for (int ks = 0; ks < 2; ks++) {
            uint4 aF[2], bF[4];
#pragma unroll
            for (int mt = 0; mt < 2; mt++) aF[mt] = s[(mt * 2 + ks) * 32];
#pragma unroll
            for (int np = 0; np < 4; np++) bF[np] = s[(4 + np * 2 + ks) * 32];
#pragma unroll
            for (int mt = 0; mt < 2; mt++) {
                uint32_t a[4] = { aF[mt].x, aF[mt].y, aF[mt].z, aF[mt].w };
#pragma unroll
                for (int np = 0; np < 4; np++) {
                    asm volatile(
                        "mma.sync.aligned.m16n8k16.row.col.f32.f16.f16.f32 "
                        "{%0,%1,%2,%3}, {%4,%5,%6,%7}, {%8,%9}, {%0,%1,%2,%3};\n"
                        : "+f"(c[mt][2 * np][0]), "+f"(c[mt][2 * np][1]),
                          "+f"(c[mt][2 * np][2]), "+f"(c[mt][2 * np][3])
                        : "r"(a[0]), "r"(a[1]), "r"(a[2]), "r"(a[3]),
                          "r"(bF[np].x), "r"(bF[np].y));
                    asm volatile(
                        "mma.sync.aligned.m16n8k16.row.col.f32.f16.f16.f32 "
                        "{%0,%1,%2,%3}, {%4,%5,%6,%7}, {%8,%9}, {%0,%1,%2,%3};\n"
                        : "+f"(c[mt][2 * np + 1][0]), "+f"(c[mt][2 * np + 1][1]),
                          "+f"(c[mt][2 * np + 1][2]), "+f"(c[mt][2 * np + 1][3])
                        : "r"(a[0]), "r"(a[1]), "r"(a[2]), "r"(a[3]),
                          "r"(bF[np].z), "r"(bF[np].w));
                }
            }
        }
    };

    issue(0, 0);
    issue(1, 1);

    for (int kt = 0; kt < NK; kt++) {
        if (kt <= NK - 2) { CP_WAIT1(); }   // group kt retired (per-warp)
        else              { CP_WAIT0(); }
        const int st = kt & 1;
        consume(st);
        if (kt + 2 < NK) issue(kt + 2, st);  // reuse stage just consumed
    }

    // ---- epilogue: +bias, fp32 store ----
    const int m_base = blockIdx.y * 128 + wm * 32;
    const int n_base = blockIdx.x * 128 + wn * 64;
#pragma unroll
    for (int mt = 0; mt < 2; mt++) {
        int row0 = m_base + mt * 16 + (lane >> 2);
#pragma unroll
        for (int nt = 0; nt < 8; nt++) {
            int col0 = n_base + nt * 8 + 2 * (lane & 3);
            float b0 = out_b[col0], b1 = out_b[col0 + 1];
            float2 v0 = make_float2(c[mt][nt][0] + b0, c[mt][nt][1] + b1);
            float2 v1 = make_float2(c[mt][nt][2] + b0, c[mt][nt][3] + b1);
            *(float2*)(out + (size_t)row0 * VOCAB + col0)       = v0;
            *(float2*)(out + (size_t)(row0 + 8) * VOCAB + col0) = v1;
        }
    }
}

// ---------------- launcher ----------------
extern "C" void kernel_launch(void* const* d_in, const int* in_sizes, int n_in,
                              void* d_out, int out_size) {
    const float* enc    = (const float*)d_in[0];
    const float* pred   = (const float*)d_in[1];
    const float* enc_w  = (const float*)d_in[2];
    const float* enc_b  = (const float*)d_in[3];
    const float* pred_w = (const float*)d_in[4];
    const float* pred_b = (const float*)d_in[5];
    const float* out_w  = (const float*)d_in[6];
    const float* out_b  = (const float*)d_in[7];
    float* out = (float*)d_out;

    float *E, *P;
    __half *Wt, *Zf;
    cudaGetSymbolAddress((void**)&E,  g_E);
    cudaGetSymbolAddress((void**)&P,  g_P);
    cudaGetSymbolAddress((void**)&Wt, g_Wt);
    cudaGetSymbolAddress((void**)&Zf, g_Zf);

    // projections only (200 blocks)
    prep_kernel<<<200, 256>>>(enc, pred, enc_w, enc_b, pred_w, pred_b, E, P);
    // zgen (1024) + wprep (320) in one launch
    zgen_kernel<<<1344, 256>>>(E, P, out_w, Zf, Wt);
    // 128x128 barrier-free GEMM, per-warp depth-2, 2 CTAs/SM
    cudaFuncSetAttribute(gemm_kernel,
                         cudaFuncAttributeMaxDynamicSharedMemorySize, GEMM_SMEM_BYTES);
    dim3 grd(VOCAB / 128, M_TOTAL / 128);   // (8, 512)
    gemm_kernel<<<grd, 256, GEMM_SMEM_BYTES>>>(Zf, Wt, out_b, out);
}

// round 16
// speedup vs baseline: 1.1111x; 1.1111x over previous
#include <cuda_runtime.h>
#include <cuda_fp16.h>
#include <cstdint>

#define D_MODEL 512
#define JOINT   640
#define VOCAB   1024
#define BB      4
#define TT      256
#define UU      64
#define M_TOTAL (BB*TT*UU)   // 65536

#define BM 64
#define BN 256
#define BK 32
#define NK (JOINT/BK)        // 20

// ---------------- scratch (no allocations allowed) ----------------
__device__ float  g_E[BB*TT*JOINT];       // permuted fp32 E projection
__device__ float  g_P[BB*UU*JOINT];       // permuted fp32 P projection
// Wt: fp16 out_w, m16n8k16 paired-B fragment order:
//   uint4 slot ((nblk*NK+kt)*1024 + nbp*64 + ks*32 + lane)
__device__ __half g_Wt[VOCAB*JOINT];
// Zf: fp16 tanh(E+P), A-fragment order:
//   uint4 slot ((bt*NK+kt)*256 + (rb*2+ks)*32 + lane)
__device__ __half g_Zf[(size_t)M_TOTAL*JOINT];

// ---------------- helpers ----------------
__device__ __forceinline__ float tanh_fast(float x) {
    float y;
    asm("tanh.approx.f32 %0, %1;" : "=f"(y) : "f"(x));
    return y;
}
__device__ __forceinline__ uint32_t smem_u32(const void* p) {
    return (uint32_t)__cvta_generic_to_shared(p);
}
__device__ __forceinline__ void cp_async16(void* smem_dst, const void* gmem_src) {
    asm volatile("cp.async.cg.shared.global [%0], [%1], 16;\n"
                 :: "r"(smem_u32(smem_dst)), "l"(gmem_src));
}
#define CP_COMMIT() asm volatile("cp.async.commit_group;\n" ::: "memory")
#define CP_WAIT0()  asm volatile("cp.async.wait_group 0;\n" ::: "memory")
#define CP_WAIT1()  asm volatile("cp.async.wait_group 1;\n" ::: "memory")

// ---------------- projection tile into smem: sT[m][j] = X[m]·W[j] + b[j] ----
__device__ void proj_tile_smem(const float* __restrict__ X, const float* __restrict__ W,
                               const float* __restrict__ bias,
                               float (*sT)[68], int m0, int j0) {
    __shared__ float sX[16][68];   // [k][m]
    __shared__ float sW[16][68];   // [k][j]
    const int tid = threadIdx.x;
    const int tx = tid & 15, ty = tid >> 4;
    const int lrow = tid >> 2, lseg = tid & 3;

    float acc[4][4] = {};
    for (int k0 = 0; k0 < D_MODEL; k0 += 16) {
        float4 xv = *(const float4*)(X + (size_t)(m0 + lrow) * D_MODEL + k0 + lseg * 4);
        float4 wv = *(const float4*)(W + (size_t)(j0 + lrow) * D_MODEL + k0 + lseg * 4);
        sX[lseg * 4 + 0][lrow] = xv.x; sX[lseg * 4 + 1][lrow] = xv.y;
        sX[lseg * 4 + 2][lrow] = xv.z; sX[lseg * 4 + 3][lrow] = xv.w;
        sW[lseg * 4 + 0][lrow] = wv.x; sW[lseg * 4 + 1][lrow] = wv.y;
        sW[lseg * 4 + 2][lrow] = wv.z; sW[lseg * 4 + 3][lrow] = wv.w;
        __syncthreads();
#pragma unroll
        for (int k = 0; k < 16; k++) {
            float4 a = *(const float4*)(&sX[k][ty * 4]);
            float4 b = *(const float4*)(&sW[k][tx * 4]);
            float av[4] = { a.x, a.y, a.z, a.w };
            float bv[4] = { b.x, b.y, b.z, b.w };
#pragma unroll
            for (int i = 0; i < 4; i++)
#pragma unroll
                for (int j = 0; j < 4; j++) acc[i][j] += av[i] * bv[j];
        }
        __syncthreads();
    }
    float4 bv = *(const float4*)(bias + j0 + tx * 4);
    float bb[4] = { bv.x, bv.y, bv.z, bv.w };
#pragma unroll
    for (int i = 0; i < 4; i++)
#pragma unroll
        for (int j = 0; j < 4; j++)
            sT[ty * 4 + i][tx * 4 + j] = acc[i][j] + bb[j];
    __syncthreads();
}

// ---------------- kernel 1: projections only (E + P), permuted outputs -------
// bid [0,160): E proj tiles  [160,200): P proj tiles
__global__ void __launch_bounds__(256) prep_kernel(
    const float* __restrict__ enc,    const float* __restrict__ pred,
    const float* __restrict__ enc_w,  const float* __restrict__ enc_b,
    const float* __restrict__ pred_w, const float* __restrict__ pred_b,
    float* __restrict__ E, float* __restrict__ Pq) {
    const int bid = blockIdx.x;
    const int tid = threadIdx.x;
    __shared__ float sT[64][68];

    if (bid < 160) {
        int m0 = (bid / 10) * 64, j0 = (bid % 10) * 64;
        proj_tile_smem(enc, enc_w, enc_b, sT, m0, j0);
#pragma unroll
        for (int i = 0; i < 4; i++) {
            int sid = tid + 256 * i;
            int row = sid >> 4;
            int sl  = sid & 15;
            int kt_l = sl >> 3, ks = (sl >> 2) & 1, tg = sl & 3;
            int col = kt_l * 32 + ks * 16 + 2 * tg;
            float4 v;
            v.x = sT[row][col];     v.y = sT[row][col + 1];
            v.z = sT[row][col + 8]; v.w = sT[row][col + 9];
            *(float4*)(E + (size_t)(m0 + row) * JOINT + j0 + kt_l * 32
                         + (ks * 4 + tg) * 4) = v;
        }
    } else {
        int idx = bid - 160;                      // 40 tiles: 4 b x 10 j
        int b  = idx / 10;
        int j0 = (idx % 10) * 64;
        proj_tile_smem(pred, pred_w, pred_b, sT, b * 64, j0);
#pragma unroll
        for (int i = 0; i < 4; i++) {
            int sid = tid + 256 * i;
            int kt_l = sid >> 9;
            int pidx = sid & 511;
            int part = pidx >> 8;
            int ptid = pidx & 255;
            int blk = ptid >> 5;
            int rb = blk >> 1, ks = blk & 1;
            int g = (ptid >> 2) & 7, tg = ptid & 3;
            int u = rb * 16 + g + part * 8;
            int col = kt_l * 32 + ks * 16 + 2 * tg;
            float4 v;
            v.x = sT[u][col];     v.y = sT[u][col + 1];
            v.z = sT[u][col + 8]; v.w = sT[u][col + 9];
            *(float4*)(Pq + ((size_t)(b * NK + (j0 >> 5) + kt_l) * 512 + pidx) * 4) = v;
        }
    }
}

// ---------------- kernel 2: zgen (blocks 0..1023) + wprep (1024..1343) -------
__global__ void __launch_bounds__(256) zgen_kernel(
    const float* __restrict__ E, const float* __restrict__ P,
    const float* __restrict__ out_w,
    __half* __restrict__ Zf, __half* __restrict__ Wt) {
    const int tid = threadIdx.x;
    const int bid = blockIdx.x;

    if (bid >= 1024) {
        // ---- wprep: fp16-convert + paired-B fragment permute of out_w ----
        int s = (bid - 1024) * 256 + tid;         // 16B-slot index, 81920 total
        int lane = s & 31;
        int t1 = s >> 5;
        int ks  = t1 & 1;  t1 >>= 1;
        int nbp = t1 & 15; t1 >>= 4;
        int kt  = t1 % NK;
        int nblk = t1 / NK;
        int g = lane >> 2, tg = lane & 3;
        int v = nblk * 256 + nbp * 16 + g;
        int k = kt * 32 + ks * 16 + 2 * tg;
        const float* w0 = out_w + (size_t)v * JOINT;
        const float* w1 = w0 + (size_t)8 * JOINT;
        float2 aa = *(const float2*)(w0 + k);
        float2 ab = *(const float2*)(w0 + k + 8);
        float2 ba = *(const float2*)(w1 + k);
        float2 bb = *(const float2*)(w1 + k + 8);
        __half2 h0 = __floats2half2_rn(aa.x, aa.y);
        __half2 h1 = __floats2half2_rn(ab.x, ab.y);
        __half2 h2 = __floats2half2_rn(ba.x, ba.y);
        __half2 h3 = __floats2half2_rn(bb.x, bb.y);
        uint4 o;
        o.x = *(const uint32_t*)&h0; o.y = *(const uint32_t*)&h1;
        o.z = *(const uint32_t*)&h2; o.w = *(const uint32_t*)&h3;
        *(uint4*)(Wt + (size_t)s * 8) = o;
        return;
    }

    // ---- zgen: Zf = fp16(tanh(E+P)) in A-fragment order ----
    const int bt  = bid;
    const int b_  = bt >> 8;
    const int ks_p = (tid >> 5) & 1;
    const int tg_p = tid & 3;
    const float* gEp  = E + (size_t)bt * JOINT + (ks_p * 4 + tg_p) * 4;
    const float* gP0p = P + ((size_t)(b_ * NK) * 512 + tid) * 4;
    uint4* dst = (uint4*)Zf + (size_t)bt * NK * 256 + tid;

#pragma unroll 4
    for (int kt = 0; kt < NK; kt++) {
        float4 eV  = *(const float4*)(gEp  + (size_t)kt * 32);
        float4 p0V = *(const float4*)(gP0p + (size_t)kt * 2048);
        float4 p1V = *(const float4*)(gP0p + (size_t)kt * 2048 + 1024);
        __half2 a0 = __floats2half2_rn(tanh_fast(eV.x + p0V.x), tanh_fast(eV.y + p0V.y));
        __half2 a1 = __floats2half2_rn(tanh_fast(eV.x + p1V.x), tanh_fast(eV.y + p1V.y));
        __half2 a2 = __floats2half2_rn(tanh_fast(eV.z + p0V.z), tanh_fast(eV.w + p0V.w));
        __half2 a3 = __floats2half2_rn(tanh_fast(eV.z + p1V.z), tanh_fast(eV.w + p1V.w));
        uint4 st;
        st.x = *(const uint32_t*)&a0; st.y = *(const uint32_t*)&a1;
        st.z = *(const uint32_t*)&a2; st.w = *(const uint32_t*)&a3;
        dst[kt * 256] = st;
    }
}

// ---------------- kernel 3: 64x256 barrier-free GEMM ----------------
// Round-12 skeleton: 8 warps, wm = warp>>2 (0..1, 32-row), wn = warp&3 (0..3,
// 64-col). B staged per-warp via cp.async depth-2 (8 slots: np*2+ks); A kept in
// REGISTERS, prefetched one full chunk ahead via LDG.128 (L1/L2-hit).
// smem: [warp][stage 0..1][slot 0..7][lane] uint4 = 64KB -> 2 CTAs/SM.
#define DSTAGE 2
#define BSLOTS 8
#define GEMM_SMEM_BYTES (8 * DSTAGE * BSLOTS * 32 * 16)   // 65536

__global__ void __launch_bounds__(256, 2) gemm_kernel(
    const __half* __restrict__ Zf, const __half* __restrict__ Wt,
    const float* __restrict__ out_b, float* __restrict__ out) {

    extern __shared__ uint4 smq[];

    const int tid  = threadIdx.x;
    const int warp = tid >> 5;
    const int lane = tid & 31;
    const int wm = warp >> 2;       // 0..1 : 32-row slab
    const int wn = warp & 3;        // 0..3 : 64-col slab

    const int bt   = blockIdx.y;    // 0..1023
    const int nblk = blockIdx.x;    // 0..3

    const uint4* Ab = (const uint4*)Zf + (size_t)bt * NK * 256
                      + (size_t)(wm * 2) * 64 + lane;
    const uint4* Bb = (const uint4*)Wt + (size_t)nblk * NK * 1024
                      + (size_t)(wn * 4) * 64 + lane;

    uint4* const ws = smq + (size_t)warp * (DSTAGE * BSLOTS * 32) + lane;

    auto issueB = [&](int kt, int stage) {
        uint4* dst = ws + stage * (BSLOTS * 32);
        const uint4* b = Bb + (size_t)kt * 1024;
#pragma unroll
        for (int np = 0; np < 4; np++)
#pragma unroll
            for (int ks = 0; ks < 2; ks++)
                cp_async16(dst + (np * 2 + ks) * 32, b + np * 64 + ks * 32);
        CP_COMMIT();
    };

    auto loadA = [&](int kt, uint4 a[2][2]) {
        const uint4* p = Ab + (size_t)kt * 256;
#pragma unroll
        for (int mt = 0; mt < 2; mt++)
#pragma unroll
            for (int ks = 0; ks < 2; ks++)
                a[mt][ks] = p[mt * 64 + ks * 32];
    };

    float c[2][8][4];
#pragma unroll
    for (int mt = 0; mt < 2; mt++)
#pragma unroll
        for (int nt = 0; nt < 8; nt++)
#pragma unroll
            for (int qq = 0; qq < 4; qq++) c[mt][nt][qq] = 0.0f;

    auto consume = [&](int stage, uint4 aF[2][2]) {
        const uint4* s = ws + stage * (BSLOTS * 32);
#pragma unroll
        for (int ks = 0; ks < 2; ks++) {
            uint4 bF[4];
#pragma unroll
            for (int np = 0; np < 4; np++) bF[np] = s[(np * 2 + ks) * 32];
#pragma unroll
            for (int mt = 0; mt < 2; mt++) {
                uint32_t a[4] = { aF[mt][ks].x, aF[mt][ks].y,
                                  aF[mt][ks].z, aF[mt][ks].w };
#pragma unroll
                for (int np = 0; np < 4; np++) {
                    asm volatile(
                        "mma.sync.aligned.m16n8k16.row.col.f32.f16.f16.f32 "
                        "{%0,%1,%2,%3}, {%4,%5,%6,%7}, {%8,%9}, {%0,%1,%2,%3};\n"
                        : "+f"(c[mt][2 * np][0]), "+f"(c[mt][2 * np][1]),
                          "+f"(c[mt][2 * np][2]), "+f"(c[mt][2 * np][3])
                        : "r"(a[0]), "r"(a[1]), "r"(a[2]), "r"(a[3]),
                          "r"(bF[np].x), "r"(bF[np].y));
                    asm volatile(
                        "mma.sync.aligned.m16n8k16.row.col.f32.f16.f16.f32 "
                        "{%0,%1,%2,%3}, {%4,%5,%6,%7}, {%8,%9}, {%0,%1,%2,%3};\n"
                        : "+f"(c[mt][2 * np + 1][0]), "+f"(c[mt][2 * np + 1][1]),
                          "+f"(c[mt][2 * np + 1][2]), "+f"(c[mt][2 * np + 1][3])
                        : "r"(a[0]), "r"(a[1]), "r"(a[2]), "r"(a[3]),
                          "r"(bF[np].z), "r"(bF[np].w));
                }
            }
        }
    };

    uint4 aCur[2][2], aNxt[2][2];
    loadA(0, aCur);
    issueB(0, 0);
    issueB(1, 1);

    for (int kt = 0; kt < NK; kt++) {
        // prefetch next A chunk in registers (full-chunk distance)
        if (kt + 1 < NK) loadA(kt + 1, aNxt);

        if (kt <= NK - 2) { CP_WAIT1(); }   // B group kt retired (per-warp)
        else              { CP_WAIT0(); }
        const int st = kt & 1;
        consume(st, aCur);
        if (kt + 2 < NK) issueB(kt + 2, st);

#pragma unroll
        for (int mt = 0; mt < 2; mt++)
#pragma unroll
            for (int ks = 0; ks < 2; ks++)
                aCur[mt][ks] = aNxt[mt][ks];
    }

    // ---- epilogue: +bias, fp32 store ----
    const int m_base = bt * BM + wm * 32;
    const int n_base = nblk * BN + wn * 64;
#pragma unroll
    for (int mt = 0; mt < 2; mt++) {
        int row0 = m_base + mt * 16 + (lane >> 2);
#pragma unroll
        for (int nt = 0; nt < 8; nt++) {
            int col0 = n_base + nt * 8 + 2 * (lane & 3);
            float b0 = out_b[col0], b1 = out_b[col0 + 1];
            float2 v0 = make_float2(c[mt][nt][0] + b0, c[mt][nt][1] + b1);
            float2 v1 = make_float2(c[mt][nt][2] + b0, c[mt][nt][3] + b1);
            *(float2*)(out + (size_t)row0 * VOCAB + col0)       = v0;
            *(float2*)(out + (size_t)(row0 + 8) * VOCAB + col0) = v1;
        }
    }
}

// ---------------- launcher ----------------
extern "C" void kernel_launch(void* const* d_in, const int* in_sizes, int n_in,
                              void* d_out, int out_size) {
    const float* enc    = (const float*)d_in[0];
    const float* pred   = (const float*)d_in[1];
    const float* enc_w  = (const float*)d_in[2];
    const float* enc_b  = (const float*)d_in[3];
    const float* pred_w = (const float*)d_in[4];
    const float* pred_b = (const float*)d_in[5];
    const float* out_w  = (const float*)d_in[6];
    const float* out_b  = (const float*)d_in[7];
    float* out = (float*)d_out;

    float *E, *P;
    __half *Wt, *Zf;
    cudaGetSymbolAddress((void**)&E,  g_E);
    cudaGetSymbolAddress((void**)&P,  g_P);
    cudaGetSymbolAddress((void**)&Wt, g_Wt);
    cudaGetSymbolAddress((void**)&Zf, g_Zf);

    // projections only (200 blocks)
    prep_kernel<<<200, 256>>>(enc, pred, enc_w, enc_b, pred_w, pred_b, E, P);
    // zgen (1024) + wprep (320) in one launch
    zgen_kernel<<<1344, 256>>>(E, P, out_w, Zf, Wt);
    // 64x256 barrier-free GEMM: B staged depth-2, A register-prefetched
    cudaFuncSetAttribute(gemm_kernel,
                         cudaFuncAttributeMaxDynamicSharedMemorySize, GEMM_SMEM_BYTES);
    dim3 grd(VOCAB / BN, M_TOTAL / BM);   // (4, 1024)
    gemm_kernel<<<grd, 256, GEMM_SMEM_BYTES>>>(Zf, Wt, out_b, out);
}

// round 17
// speedup vs baseline: 1.1523x; 1.0371x over previous
#include <cuda_runtime.h>
#include <cuda_fp16.h>
#include <cstdint>

#define D_MODEL 512
#define JOINT   640
#define VOCAB   1024
#define BB      4
#define TT      256
#define UU      64
#define M_TOTAL (BB*TT*UU)   // 65536

#define BM 64
#define BN 256
#define BK 32
#define NK (JOINT/BK)        // 20

// ---------------- scratch (no allocations allowed) ----------------
__device__ float  g_E[BB*TT*JOINT];       // permuted fp32 E projection
__device__ float  g_P[BB*UU*JOINT];       // permuted fp32 P projection
// Wt: fp16 out_w, m16n8k16 paired-B fragment order:
//   uint4 slot ((nblk*NK+kt)*1024 + nbp*64 + ks*32 + lane)
__device__ __half g_Wt[VOCAB*JOINT];
// Zf: fp16 tanh(E+P), A-fragment order:
//   uint4 slot ((bt*NK+kt)*256 + (rb*2+ks)*32 + lane)
__device__ __half g_Zf[(size_t)M_TOTAL*JOINT];

// ---------------- helpers ----------------
__device__ __forceinline__ float tanh_fast(float x) {
    float y;
    asm("tanh.approx.f32 %0, %1;" : "=f"(y) : "f"(x));
    return y;
}
__device__ __forceinline__ uint32_t smem_u32(const void* p) {
    return (uint32_t)__cvta_generic_to_shared(p);
}
__device__ __forceinline__ void cp_async16(void* smem_dst, const void* gmem_src) {
    asm volatile("cp.async.cg.shared.global [%0], [%1], 16;\n"
                 :: "r"(smem_u32(smem_dst)), "l"(gmem_src));
}
#define CP_COMMIT() asm volatile("cp.async.commit_group;\n" ::: "memory")
#define CP_WAIT0()  asm volatile("cp.async.wait_group 0;\n" ::: "memory")
#define CP_WAIT1()  asm volatile("cp.async.wait_group 1;\n" ::: "memory")

// ---------------- projection tile into smem: sT[m][j] = X[m]·W[j] + b[j] ----
__device__ void proj_tile_smem(const float* __restrict__ X, const float* __restrict__ W,
                               const float* __restrict__ bias,
                               float (*sT)[68], int m0, int j0) {
    __shared__ float sX[16][68];   // [k][m]
    __shared__ float sW[16][68];   // [k][j]
    const int tid = threadIdx.x;
    const int tx = tid & 15, ty = tid >> 4;
    const int lrow = tid >> 2, lseg = tid & 3;

    float acc[4][4] = {};
    for (int k0 = 0; k0 < D_MODEL; k0 += 16) {
        float4 xv = *(const float4*)(X + (size_t)(m0 + lrow) * D_MODEL + k0 + lseg * 4);
        float4 wv = *(const float4*)(W + (size_t)(j0 + lrow) * D_MODEL + k0 + lseg * 4);
        sX[lseg * 4 + 0][lrow] = xv.x; sX[lseg * 4 + 1][lrow] = xv.y;
        sX[lseg * 4 + 2][lrow] = xv.z; sX[lseg * 4 + 3][lrow] = xv.w;
        sW[lseg * 4 + 0][lrow] = wv.x; sW[lseg * 4 + 1][lrow] = wv.y;
        sW[lseg * 4 + 2][lrow] = wv.z; sW[lseg * 4 + 3][lrow] = wv.w;
        __syncthreads();
#pragma unroll
        for (int k = 0; k < 16; k++) {
            float4 a = *(const float4*)(&sX[k][ty * 4]);
            float4 b = *(const float4*)(&sW[k][tx * 4]);
            float av[4] = { a.x, a.y, a.z, a.w };
            float bv[4] = { b.x, b.y, b.z, b.w };
#pragma unroll
            for (int i = 0; i < 4; i++)
#pragma unroll
                for (int j = 0; j < 4; j++) acc[i][j] += av[i] * bv[j];
        }
        __syncthreads();
    }
    float4 bv = *(const float4*)(bias + j0 + tx * 4);
    float bb[4] = { bv.x, bv.y, bv.z, bv.w };
#pragma unroll
    for (int i = 0; i < 4; i++)
#pragma unroll
        for (int j = 0; j < 4; j++)
            sT[ty * 4 + i][tx * 4 + j] = acc[i][j] + bb[j];
    __syncthreads();
}

// ---------------- kernel 1: projections only (E + P), permuted outputs -------
// bid [0,160): E proj tiles  [160,200): P proj tiles
__global__ void __launch_bounds__(256) prep_kernel(
    const float* __restrict__ enc,    const float* __restrict__ pred,
    const float* __restrict__ enc_w,  const float* __restrict__ enc_b,
    const float* __restrict__ pred_w, const float* __restrict__ pred_b,
    float* __restrict__ E, float* __restrict__ Pq) {
    const int bid = blockIdx.x;
    const int tid = threadIdx.x;
    __shared__ float sT[64][68];

    if (bid < 160) {
        int m0 = (bid / 10) * 64, j0 = (bid % 10) * 64;
        proj_tile_smem(enc, enc_w, enc_b, sT, m0, j0);
#pragma unroll
        for (int i = 0; i < 4; i++) {
            int sid = tid + 256 * i;
            int row = sid >> 4;
            int sl  = sid & 15;
            int kt_l = sl >> 3, ks = (sl >> 2) & 1, tg = sl & 3;
            int col = kt_l * 32 + ks * 16 + 2 * tg;
            float4 v;
            v.x = sT[row][col];     v.y = sT[row][col + 1];
            v.z = sT[row][col + 8]; v.w = sT[row][col + 9];
            *(float4*)(E + (size_t)(m0 + row) * JOINT + j0 + kt_l * 32
                         + (ks * 4 + tg) * 4) = v;
        }
    } else {
        int idx = bid - 160;                      // 40 tiles: 4 b x 10 j
        int b  = idx / 10;
        int j0 = (idx % 10) * 64;
        proj_tile_smem(pred, pred_w, pred_b, sT, b * 64, j0);
#pragma unroll
        for (int i = 0; i < 4; i++) {
            int sid = tid + 256 * i;
            int kt_l = sid >> 9;
            int pidx = sid & 511;
            int part = pidx >> 8;
            int ptid = pidx & 255;
            int blk = ptid >> 5;
            int rb = blk >> 1, ks = blk & 1;
            int g = (ptid >> 2) & 7, tg = ptid & 3;
            int u = rb * 16 + g + part * 8;
            int col = kt_l * 32 + ks * 16 + 2 * tg;
            float4 v;
            v.x = sT[u][col];     v.y = sT[u][col + 1];
            v.z = sT[u][col + 8]; v.w = sT[u][col + 9];
            *(float4*)(Pq + ((size_t)(b * NK + (j0 >> 5) + kt_l) * 512 + pidx) * 4) = v;
        }
    }
}

// ---------------- kernel 2: zgen (blocks 0..1023) + wprep (1024..1343) -------
__global__ void __launch_bounds__(256) zgen_kernel(
    const float* __restrict__ E, const float* __restrict__ P,
    const float* __restrict__ out_w,
    __half* __restrict__ Zf, __half* __restrict__ Wt) {
    const int tid = threadIdx.x;
    const int bid = blockIdx.x;

    if (bid >= 1024) {
        // ---- wprep: fp16-convert + paired-B fragment permute of out_w ----
        int s = (bid - 1024) * 256 + tid;         // 16B-slot index, 81920 total
        int lane = s & 31;
        int t1 = s >> 5;
        int ks  = t1 & 1;  t1 >>= 1;
        int nbp = t1 & 15; t1 >>= 4;
        int kt  = t1 % NK;
        int nblk = t1 / NK;
        int g = lane >> 2, tg = lane & 3;
        int v = nblk * 256 + nbp * 16 + g;
        int k = kt * 32 + ks * 16 + 2 * tg;
        const float* w0 = out_w + (size_t)v * JOINT;
        const float* w1 = w0 + (size_t)8 * JOINT;
        float2 aa = *(const float2*)(w0 + k);
        float2 ab = *(const float2*)(w0 + k + 8);
        float2 ba = *(const float2*)(w1 + k);
        float2 bb = *(const float2*)(w1 + k + 8);
        __half2 h0 = __floats2half2_rn(aa.x, aa.y);
        __half2 h1 = __floats2half2_rn(ab.x, ab.y);
        __half2 h2 = __floats2half2_rn(ba.x, ba.y);
        __half2 h3 = __floats2half2_rn(bb.x, bb.y);
        uint4 o;
        o.x = *(const uint32_t*)&h0; o.y = *(const uint32_t*)&h1;
        o.z = *(const uint32_t*)&h2; o.w = *(const uint32_t*)&h3;
        *(uint4*)(Wt + (size_t)s * 8) = o;
        return;
    }

    // ---- zgen: Zf = fp16(tanh(E+P)) in A-fragment order ----
    const int bt  = bid;
    const int b_  = bt >> 8;
    const int ks_p = (tid >> 5) & 1;
    const int tg_p = tid & 3;
    const float* gEp  = E + (size_t)bt * JOINT + (ks_p * 4 + tg_p) * 4;
    const float* gP0p = P + ((size_t)(b_ * NK) * 512 + tid) * 4;
    uint4* dst = (uint4*)Zf + (size_t)bt * NK * 256 + tid;

#pragma unroll 4
    for (int kt = 0; kt < NK; kt++) {
        float4 eV  = *(const float4*)(gEp  + (size_t)kt * 32);
        float4 p0V = *(const float4*)(gP0p + (size_t)kt * 2048);
        float4 p1V = *(const float4*)(gP0p + (size_t)kt * 2048 + 1024);
        __half2 a0 = __floats2half2_rn(tanh_fast(eV.x + p0V.x), tanh_fast(eV.y + p0V.y));
        __half2 a1 = __floats2half2_rn(tanh_fast(eV.x + p1V.x), tanh_fast(eV.y + p1V.y));
        __half2 a2 = __floats2half2_rn(tanh_fast(eV.z + p0V.z), tanh_fast(eV.w + p0V.w));
        __half2 a3 = __floats2half2_rn(tanh_fast(eV.z + p1V.z), tanh_fast(eV.w + p1V.w));
        uint4 st;
        st.x = *(const uint32_t*)&a0; st.y = *(const uint32_t*)&a1;
        st.z = *(const uint32_t*)&a2; st.w = *(const uint32_t*)&a3;
        dst[kt * 256] = st;
    }
}

// ---------------- kernel 3: 64x256 barrier-free GEMM (round-12 structure) ----
// 8 warps: wm = warp>>2 (0..1, 32-row slab), wn = warp&3 (0..3, 64-col slab).
// Per warp per chunk: 12 staged slots (4 A: mt*2+ks ; 8 B: 4+np*2+ks), 32 MMAs.
// smem: [warp][stage 0..1][slot 0..11][lane] uint4 = 96KB -> 2 CTAs/SM.
// Depth-2, per-warp wait_group, NO block barriers.
#define DSTAGE 2
#define SLOTS  12
#define GEMM_SMEM_BYTES (8 * DSTAGE * SLOTS * 32 * 16)   // 98304

__global__ void __launch_bounds__(256, 2) gemm_kernel(
    const __half* __restrict__ Zf, const __half* __restrict__ Wt,
    const float* __restrict__ out_b, float* __restrict__ out) {

    extern __shared__ uint4 smq[];

    const int tid  = threadIdx.x;
    const int warp = tid >> 5;
    const int lane = tid & 31;
    const int wm = warp >> 2;       // 0..1 : 32-row slab
    const int wn = warp & 3;        // 0..3 : 64-col slab

    const int bt   = blockIdx.y;    // 0..1023
    const int nblk = blockIdx.x;    // 0..3

    const uint4* Ab = (const uint4*)Zf + (size_t)bt * NK * 256
                      + (size_t)(wm * 2) * 64 + lane;
    const uint4* Bb = (const uint4*)Wt + (size_t)nblk * NK * 1024
                      + (size_t)(wn * 4) * 64 + lane;

    uint4* const ws = smq + (size_t)warp * (DSTAGE * SLOTS * 32) + lane;

    auto issue = [&](int kt, int stage) {
        uint4* dst = ws + stage * (SLOTS * 32);
        const uint4* a = Ab + (size_t)kt * 256;
        const uint4* b = Bb + (size_t)kt * 1024;
#pragma unroll
        for (int mt = 0; mt < 2; mt++)
#pragma unroll
            for (int ks = 0; ks < 2; ks++)
                cp_async16(dst + (mt * 2 + ks) * 32, a + mt * 64 + ks * 32);
#pragma unroll
        for (int np = 0; np < 4; np++)
#pragma unroll
            for (int ks = 0; ks < 2; ks++)
                cp_async16(dst + (4 + np * 2 + ks) * 32, b + np * 64 + ks * 32);
        CP_COMMIT();
    };

    float c[2][8][4];
#pragma unroll
    for (int mt = 0; mt < 2; mt++)
#pragma unroll
        for (int nt = 0; nt < 8; nt++)
#pragma unroll
            for (int qq = 0; qq < 4; qq++) c[mt][nt][qq] = 0.0f;

    auto consume = [&](int stage) {
        const uint4* s = ws + stage * (SLOTS * 32);
#pragma unroll
        for (int ks = 0; ks < 2; ks++) {
            uint4 aF[2], bF[4];
#pragma unroll
            for (int mt = 0; mt < 2; mt++) aF[mt] = s[(mt * 2 + ks) * 32];
#pragma unroll
            for (int np = 0; np < 4; np++) bF[np] = s[(4 + np * 2 + ks) * 32];
#pragma unroll
            for (int mt = 0; mt < 2; mt++) {
                uint32_t a[4] = { aF[mt].x, aF[mt].y, aF[mt].z, aF[mt].w };
#pragma unroll
                for (int np = 0; np < 4; np++) {
                    asm volatile(
                        "mma.sync.aligned.m16n8k16.row.col.f32.f16.f16.f32 "
                        "{%0,%1,%2,%3}, {%4,%5,%6,%7}, {%8,%9}, {%0,%1,%2,%3};\n"
                        : "+f"(c[mt][2 * np][0]), "+f"(c[mt][2 * np][1]),
                          "+f"(c[mt][2 * np][2]), "+f"(c[mt][2 * np][3])
                        : "r"(a[0]), "r"(a[1]), "r"(a[2]), "r"(a[3]),
                          "r"(bF[np].x), "r"(bF[np].y));
                    asm volatile(
                        "mma.sync.aligned.m16n8k16.row.col.f32.f16.f16.f32 "
                        "{%0,%1,%2,%3}, {%4,%5,%6,%7}, {%8,%9}, {%0,%1,%2,%3};\n"
                        : "+f"(c[mt][2 * np + 1][0]), "+f"(c[mt][2 * np + 1][1]),
                          "+f"(c[mt][2 * np + 1][2]), "+f"(c[mt][2 * np + 1][3])
                        : "r"(a[0]), "r"(a[1]), "r"(a[2]), "r"(a[3]),
                          "r"(bF[np].z), "r"(bF[np].w));
                }
            }
        }
    };

    issue(0, 0);
    issue(1, 1);

    for (int kt = 0; kt < NK; kt++) {
        if (kt <= NK - 2) { CP_WAIT1(); }   // group kt retired (per-warp)
        else              { CP_WAIT0(); }
        const int st = kt & 1;
        consume(st);
        if (kt + 2 < NK) issue(kt + 2, st);  // reuse stage just consumed
    }

    // ---- epilogue: +bias, fp32 store ----
    const int m_base = bt * BM + wm * 32;
    const int n_base = nblk * BN + wn * 64;
#pragma unroll
    for (int mt = 0; mt < 2; mt++) {
        int row0 = m_base + mt * 16 + (lane >> 2);
#pragma unroll
        for (int nt = 0; nt < 8; nt++) {
            int col0 = n_base + nt * 8 + 2 * (lane & 3);
            float b0 = out_b[col0], b1 = out_b[col0 + 1];
            float2 v0 = make_float2(c[mt][nt][0] + b0, c[mt][nt][1] + b1);
            float2 v1 = make_float2(c[mt][nt][2] + b0, c[mt][nt][3] + b1);
            *(float2*)(out + (size_t)row0 * VOCAB + col0)       = v0;
            *(float2*)(out + (size_t)(row0 + 8) * VOCAB + col0) = v1;
        }
    }
}

// ---------------- launcher ----------------
extern "C" void kernel_launch(void* const* d_in, const int* in_sizes, int n_in,
                              void* d_out, int out_size) {
    const float* enc    = (const float*)d_in[0];
    const float* pred   = (const float*)d_in[1];
    const float* enc_w  = (const float*)d_in[2];
    const float* enc_b  = (const float*)d_in[3];
    const float* pred_w = (const float*)d_in[4];
    const float* pred_b = (const float*)d_in[5];
    const float* out_w  = (const float*)d_in[6];
    const float* out_b  = (const float*)d_in[7];
    float* out = (float*)d_out;

    float *E, *P;
    __half *Wt, *Zf;
    cudaGetSymbolAddress((void**)&E,  g_E);
    cudaGetSymbolAddress((void**)&P,  g_P);
    cudaGetSymbolAddress((void**)&Wt, g_Wt);
    cudaGetSymbolAddress((void**)&Zf, g_Zf);

    // projections only (200 blocks) — proven 46.9us version
    prep_kernel<<<200, 256>>>(enc, pred, enc_w, enc_b, pred_w, pred_b, E, P);
    // zgen (1024) + wprep (320) in one launch
    zgen_kernel<<<1344, 256>>>(E, P, out_w, Zf, Wt);
    // round-12 GEMM: 64x256, per-warp depth-2 staging (A+B), 2 CTAs/SM
    cudaFuncSetAttribute(gemm_kernel,
                         cudaFuncAttributeMaxDynamicSharedMemorySize, GEMM_SMEM_BYTES);
    dim3 grd(VOCAB / BN, M_TOTAL / BM);   // (4, 1024)
    gemm_kernel<<<grd, 256, GEMM_SMEM_BYTES>>>(Zf, Wt, out_b, out);
}